// round 2
// baseline (speedup 1.0000x reference)
#include <cuda_runtime.h>
#include <cuda_bf16.h>
#include <cstdint>

// Problem constants (fixed shapes per reference)
#define N_NODES 100000
#define DIM     128          // D_IN == D_OUT
#define NREL    8
#define NEDGES  625000
#define KTOT    (DIM * (NREL + 1))   // 1152

// ---------------------------------------------------------------------------
// Scratch (device globals; no runtime allocation)
// ---------------------------------------------------------------------------
__device__ float g_agg[(size_t)N_NODES * (NREL * DIM)];   // 409.6 MB
__device__ int   g_deg[N_NODES * NREL];
__device__ float g_inv[N_NODES * NREL];
__device__ int   g_is32;   // 1 if edge_index/edge_type are int32, 0 if int64

// ---------------------------------------------------------------------------
// 0) dtype detection: read first 64 entries as int64; packed int32 data makes
//    these huge (high word = next random index), so any out-of-range value
//    proves int32.
// ---------------------------------------------------------------------------
__global__ void detect_kernel(const void* __restrict__ ei) {
    if (threadIdx.x == 0) {
        const long long* p = (const long long*)ei;
        int is32 = 0;
        #pragma unroll 1
        for (int i = 0; i < 64; ++i) {
            long long v = p[i];
            if (v < 0 || v >= N_NODES) { is32 = 1; break; }
        }
        g_is32 = is32;
    }
}

__device__ __forceinline__ int load_idx(const void* p, long long i, int is32) {
    if (is32) return ((const int*)p)[i];
    return (int)((const long long*)p)[i];
}

// ---------------------------------------------------------------------------
// 1) zero agg (float4 grid-stride) and deg
// ---------------------------------------------------------------------------
__global__ void zero_agg_kernel() {
    size_t n4 = (size_t)N_NODES * (NREL * DIM) / 4;
    float4 z = make_float4(0.f, 0.f, 0.f, 0.f);
    float4* p = reinterpret_cast<float4*>(g_agg);
    for (size_t i = (size_t)blockIdx.x * blockDim.x + threadIdx.x; i < n4;
         i += (size_t)gridDim.x * blockDim.x)
        p[i] = z;
}

__global__ void zero_deg_kernel() {
    int i = blockIdx.x * blockDim.x + threadIdx.x;
    if (i < N_NODES * NREL) g_deg[i] = 0;
}

// ---------------------------------------------------------------------------
// 2) per-(rel,dst) in-degree
// ---------------------------------------------------------------------------
__global__ void deg_kernel(const void* __restrict__ ei,
                           const void* __restrict__ et) {
    int e = blockIdx.x * blockDim.x + threadIdx.x;
    if (e >= NEDGES) return;
    int is32 = g_is32;
    int dst = load_idx(ei, (long long)NEDGES + e, is32);
    int r   = load_idx(et, e, is32);
    atomicAdd(&g_deg[dst * NREL + r], 1);
}

// ---------------------------------------------------------------------------
// 3) inv_deg = 1 / max(deg, 1)
// ---------------------------------------------------------------------------
__global__ void inv_kernel() {
    int i = blockIdx.x * blockDim.x + threadIdx.x;
    if (i >= N_NODES * NREL) return;
    int d = g_deg[i];
    g_inv[i] = 1.0f / (float)(d > 1 ? d : 1);
}

// ---------------------------------------------------------------------------
// 4) scatter: one warp per edge, agg[dst][rel] += x[src] * inv_deg[dst][rel]
// ---------------------------------------------------------------------------
__global__ void scatter_kernel(const float* __restrict__ x,
                               const void* __restrict__ ei,
                               const void* __restrict__ et) {
    int gtid = blockIdx.x * blockDim.x + threadIdx.x;
    int e    = gtid >> 5;
    int lane = gtid & 31;
    if (e >= NEDGES) return;

    int is32 = g_is32;
    int src = load_idx(ei, e, is32);
    int dst = load_idx(ei, (long long)NEDGES + e, is32);
    int r   = load_idx(et, e, is32);
    float s = g_inv[dst * NREL + r];

    const float4 v = reinterpret_cast<const float4*>(x + (size_t)src * DIM)[lane];
    float* o = g_agg + (size_t)dst * (NREL * DIM) + r * DIM + lane * 4;
    atomicAdd(o + 0, v.x * s);
    atomicAdd(o + 1, v.y * s);
    atomicAdd(o + 2, v.z * s);
    atomicAdd(o + 3, v.w * s);
}

// ---------------------------------------------------------------------------
// 5) SGEMM: out[N,128] = A[N,1152] * B[1152,128] + bias
//    A(n,k) = k<128 ? x[n][k] : g_agg[n][k-128]
//    B(k,j) = k<128 ? wself[k][j] : wrel_flat[(k-128)*128 + j]
//    Tile: BM=128, BN=128, BK=16; 256 threads; 8x8 microtile.
// ---------------------------------------------------------------------------
#define BM 128
#define BN 128
#define BK 16

__global__ __launch_bounds__(256) void gemm_kernel(
    const float* __restrict__ x,
    const float* __restrict__ wrel,
    const float* __restrict__ wself,
    const float* __restrict__ bias,
    float* __restrict__ out)
{
    __shared__ float As[BK][BM];    // transposed A tile
    __shared__ float Bs[BK][BN];

    const int m0  = blockIdx.x * BM;
    const int tid = threadIdx.x;
    const int tr  = tid >> 4;       // 0..15
    const int tc  = tid & 15;       // 0..15

    float acc[8][8];
    #pragma unroll
    for (int i = 0; i < 8; ++i)
        #pragma unroll
        for (int j = 0; j < 8; ++j) acc[i][j] = 0.f;

    for (int kt = 0; kt < KTOT / BK; ++kt) {
        const int k0 = kt * BK;

        // ---- load A tile: 128 rows x 16 k, 512 float4 quads, 2 per thread
        #pragma unroll
        for (int t = 0; t < 2; ++t) {
            int q    = tid + t * 256;
            int row  = q >> 2;           // 0..127
            int kq   = (q & 3) * 4;      // 0,4,8,12
            int grow = m0 + row;
            float4 v = make_float4(0.f, 0.f, 0.f, 0.f);
            if (grow < N_NODES) {
                const float* base = (k0 < DIM)
                    ? (x + (size_t)grow * DIM + k0)
                    : (g_agg + (size_t)grow * (NREL * DIM) + (k0 - DIM));
                v = *reinterpret_cast<const float4*>(base + kq);
            }
            As[kq + 0][row] = v.x;
            As[kq + 1][row] = v.y;
            As[kq + 2][row] = v.z;
            As[kq + 3][row] = v.w;
        }

        // ---- load B tile: 16 k x 128 cols, 512 quads, 2 per thread
        #pragma unroll
        for (int t = 0; t < 2; ++t) {
            int q    = tid + t * 256;
            int krow = q >> 5;           // 0..15
            int col  = (q & 31) * 4;     // 0..124
            int gk   = k0 + krow;
            const float* bsrc = (gk < DIM)
                ? (wself + (size_t)gk * DIM + col)
                : (wrel + (size_t)(gk - DIM) * DIM + col);
            *reinterpret_cast<float4*>(&Bs[krow][col]) =
                *reinterpret_cast<const float4*>(bsrc);
        }

        __syncthreads();

        #pragma unroll
        for (int kk = 0; kk < BK; ++kk) {
            float a[8], b[8];
            *reinterpret_cast<float4*>(&a[0]) =
                *reinterpret_cast<const float4*>(&As[kk][tr * 8 + 0]);
            *reinterpret_cast<float4*>(&a[4]) =
                *reinterpret_cast<const float4*>(&As[kk][tr * 8 + 4]);
            *reinterpret_cast<float4*>(&b[0]) =
                *reinterpret_cast<const float4*>(&Bs[kk][tc * 8 + 0]);
            *reinterpret_cast<float4*>(&b[4]) =
                *reinterpret_cast<const float4*>(&Bs[kk][tc * 8 + 4]);
            #pragma unroll
            for (int i = 0; i < 8; ++i)
                #pragma unroll
                for (int j = 0; j < 8; ++j)
                    acc[i][j] = fmaf(a[i], b[j], acc[i][j]);
        }

        __syncthreads();
    }

    // ---- epilogue: +bias, guarded store
    float bb[8];
    *reinterpret_cast<float4*>(&bb[0]) =
        *reinterpret_cast<const float4*>(&bias[tc * 8 + 0]);
    *reinterpret_cast<float4*>(&bb[4]) =
        *reinterpret_cast<const float4*>(&bias[tc * 8 + 4]);

    #pragma unroll
    for (int i = 0; i < 8; ++i) {
        int grow = m0 + tr * 8 + i;
        if (grow >= N_NODES) break;
        float4 v0 = make_float4(acc[i][0] + bb[0], acc[i][1] + bb[1],
                                acc[i][2] + bb[2], acc[i][3] + bb[3]);
        float4 v1 = make_float4(acc[i][4] + bb[4], acc[i][5] + bb[5],
                                acc[i][6] + bb[6], acc[i][7] + bb[7]);
        float* op = out + (size_t)grow * DIM + tc * 8;
        *reinterpret_cast<float4*>(op + 0) = v0;
        *reinterpret_cast<float4*>(op + 4) = v1;
    }
}

// ---------------------------------------------------------------------------
// launch
// inputs: 0:x(f32), 1:edge_index(int [2,E]), 2:edge_type(int [E]),
//         3:rel_weight(f32 [8,128,128]), 4:self_loop_weight(f32 [128,128]),
//         5:bias(f32 [128])
// ---------------------------------------------------------------------------
extern "C" void kernel_launch(void* const* d_in, const int* in_sizes, int n_in,
                              void* d_out, int out_size) {
    const float* x     = (const float*)d_in[0];
    const void*  ei    = d_in[1];
    const void*  et    = d_in[2];
    const float* wrel  = (const float*)d_in[3];
    const float* wself = (const float*)d_in[4];
    const float* bias  = (const float*)d_in[5];
    float*       out   = (float*)d_out;

    detect_kernel<<<1, 32>>>(ei);
    zero_agg_kernel<<<8192, 256>>>();
    zero_deg_kernel<<<(N_NODES * NREL + 255) / 256, 256>>>();
    deg_kernel<<<(NEDGES + 255) / 256, 256>>>(ei, et);
    inv_kernel<<<(N_NODES * NREL + 255) / 256, 256>>>();
    scatter_kernel<<<((size_t)NEDGES * 32 + 255) / 256, 256>>>(x, ei, et);
    gemm_kernel<<<(N_NODES + BM - 1) / BM, 256>>>(x, wrel, wself, bias, out);
}

// round 4
// speedup vs baseline: 2.4047x; 2.4047x over previous
#include <cuda_runtime.h>
#include <cuda_bf16.h>
#include <cstdint>

// Problem constants
#define N_NODES 100000
#define DIM     128
#define NREL    8
#define NEDGES  625000
#define NMAT    9            // 8 relations + self-loop
#define MTILE   64           // nodes per block in xw kernel

// ---------------------------------------------------------------------------
// Device globals (no runtime allocation)
// ---------------------------------------------------------------------------
__device__ float    g_y[(size_t)NREL * N_NODES * DIM];   // 409.6 MB
__device__ int      g_deg[N_NODES * NREL];
__device__ float    g_inv[N_NODES * NREL];
__device__ int      g_is32;
// Pre-packed B fragments: per (mat, kfrag) an 8KB chunk laid out as
// [split 2][nfrag 16][lane 32][reg 2] uint32 (bf16x2 each).
// chunk index cg = mat*8 + kfrag; u32 offset = cg*2048.
__device__ uint32_t g_wB[NMAT * 8 * 2048];                // 576 KB

// ---------------------------------------------------------------------------
// helpers
// ---------------------------------------------------------------------------
__device__ __forceinline__ uint32_t smem_u32(const void* p) {
    uint32_t a;
    asm("{ .reg .u64 t; cvta.to.shared.u64 t, %1; cvt.u32.u64 %0, t; }"
        : "=r"(a) : "l"(p));
    return a;
}
__device__ __forceinline__ uint32_t pack_bf2(__nv_bfloat16 lo, __nv_bfloat16 hi) {
    return (uint32_t)__bfloat16_as_ushort(lo) | ((uint32_t)__bfloat16_as_ushort(hi) << 16);
}
// split float2 into bf16 hi-pair and lo-pair (packed u32, element order: x=low bits)
__device__ __forceinline__ void split2(float2 v, uint32_t& h, uint32_t& l) {
    __nv_bfloat16 h0 = __float2bfloat16(v.x);
    __nv_bfloat16 h1 = __float2bfloat16(v.y);
    __nv_bfloat16 l0 = __float2bfloat16(v.x - __bfloat162float(h0));
    __nv_bfloat16 l1 = __float2bfloat16(v.y - __bfloat162float(h1));
    h = pack_bf2(h0, h1);
    l = pack_bf2(l0, l1);
}
__device__ __forceinline__ void mma_bf16(float* c, uint32_t a0, uint32_t a1,
                                         uint32_t a2, uint32_t a3,
                                         uint32_t b0, uint32_t b1) {
    asm volatile(
        "mma.sync.aligned.m16n8k16.row.col.f32.bf16.bf16.f32 "
        "{%0,%1,%2,%3}, {%4,%5,%6,%7}, {%8,%9}, {%0,%1,%2,%3};"
        : "+f"(c[0]), "+f"(c[1]), "+f"(c[2]), "+f"(c[3])
        : "r"(a0), "r"(a1), "r"(a2), "r"(a3), "r"(b0), "r"(b1));
}
__device__ __forceinline__ void cp16(uint32_t smem_dst, const void* gsrc) {
    asm volatile("cp.async.cg.shared.global [%0], [%1], 16;"
                 :: "r"(smem_dst), "l"(gsrc));
}
__device__ __forceinline__ void cp_commit() {
    asm volatile("cp.async.commit_group;" ::: "memory");
}
template <int N>
__device__ __forceinline__ void cp_wait() {
    asm volatile("cp.async.wait_group %0;" :: "n"(N) : "memory");
}

// ---------------------------------------------------------------------------
// 0) index dtype detection (int32 vs int64)
// ---------------------------------------------------------------------------
__global__ void detect_kernel(const void* __restrict__ ei) {
    if (threadIdx.x == 0) {
        const long long* p = (const long long*)ei;
        int is32 = 0;
        #pragma unroll 1
        for (int i = 0; i < 64; ++i) {
            long long v = p[i];
            if (v < 0 || v >= N_NODES) { is32 = 1; break; }
        }
        g_is32 = is32;
    }
}
__device__ __forceinline__ int load_idx(const void* p, long long i, int is32) {
    return is32 ? ((const int*)p)[i] : (int)((const long long*)p)[i];
}

// ---------------------------------------------------------------------------
// 1) weight prep: pack W (fp32 [mat][k][n]) into per-fragment bf16 hi/lo chunks
//    linear index = r<<14 | kk<<11 | s<<10 | nf<<6 | lane<<1 | j
// ---------------------------------------------------------------------------
__global__ void wprep_kernel(const float* __restrict__ wrel,
                             const float* __restrict__ wself) {
    int gid = blockIdx.x * blockDim.x + threadIdx.x;
    if (gid >= NMAT * 8 * 2048) return;
    int j  = gid & 1;
    int l  = (gid >> 1) & 31;
    int nf = (gid >> 6) & 15;
    int s  = (gid >> 10) & 1;
    int kk = (gid >> 11) & 7;
    int r  = gid >> 14;
    int t = l & 3, g = l >> 2;
    int n  = nf * 8 + g;
    int k0 = kk * 16 + t * 2 + (j ? 8 : 0);

    float w0, w1;
    if (r < 8) {
        w0 = wrel[((size_t)r * 128 + k0) * 128 + n];
        w1 = wrel[((size_t)r * 128 + k0 + 1) * 128 + n];
    } else {
        w0 = wself[(size_t)k0 * 128 + n];
        w1 = wself[(size_t)(k0 + 1) * 128 + n];
    }
    uint32_t h, lo;
    split2(make_float2(w0, w1), h, lo);
    g_wB[gid] = s ? lo : h;
}

// ---------------------------------------------------------------------------
// 2) degree
// ---------------------------------------------------------------------------
__global__ void zero_deg_kernel() {
    int i = blockIdx.x * blockDim.x + threadIdx.x;
    if (i < N_NODES * NREL) g_deg[i] = 0;
}
__global__ void deg_kernel(const void* __restrict__ ei, const void* __restrict__ et) {
    int e = blockIdx.x * blockDim.x + threadIdx.x;
    if (e >= NEDGES) return;
    int is32 = g_is32;
    int dst = load_idx(ei, (long long)NEDGES + e, is32);
    int r   = load_idx(et, e, is32);
    atomicAdd(&g_deg[dst * NREL + r], 1);
}
__global__ void inv_kernel() {
    int i = blockIdx.x * blockDim.x + threadIdx.x;
    if (i >= N_NODES * NREL) return;
    int d = g_deg[i];
    g_inv[i] = 1.0f / (float)(d > 1 ? d : 1);
}

// ---------------------------------------------------------------------------
// 3) xw kernel: per block of 64 nodes compute y_r = x@W_r (r<8, into g_y)
//    and out = x@W_self + bias (r==8). mma.sync bf16, 3-product split.
//    8 warps: wm = wid&3 (M 16-rows), wn = wid>>2 (N 64-cols).
// ---------------------------------------------------------------------------
__global__ __launch_bounds__(256) void xw_kernel(
    const float* __restrict__ x,
    const float* __restrict__ bias,
    float* __restrict__ out)
{
    __shared__ uint32_t sA[2][4][8][32][4];   // [split][mfrag][kfrag][lane][reg] 32KB
    __shared__ uint32_t sB[2][2][16][32][2];  // [buf][split][nfrag][lane][reg]  16KB

    const int tid  = threadIdx.x;
    const int wid  = tid >> 5;
    const int lane = tid & 31;
    const int g    = lane >> 2;
    const int t    = lane & 3;
    const int wm   = wid & 3;
    const int wn   = wid >> 2;
    const int m0   = blockIdx.x * MTILE;

    // ---- prefetch chunk 0 of B (mat 0, kfrag 0)
    {
        uint32_t sb = smem_u32(&sB[0][0][0][0][0]);
        const char* src = (const char*)g_wB;
        cp16(sb + tid * 16, src + tid * 16);
        cp16(sb + 4096 + tid * 16, src + 4096 + tid * 16);
        cp_commit();
    }

    // ---- fill A fragments (hi/lo) in SMEM
    {
        int mf  = wid & 3;
        int kk0 = (wid >> 2) * 4;
        int row0 = m0 + mf * 16 + g;
        int row1 = row0 + 8;
        bool v0 = row0 < N_NODES, v1 = row1 < N_NODES;
        const float* xr0 = x + (size_t)row0 * DIM;
        const float* xr1 = x + (size_t)row1 * DIM;
        #pragma unroll
        for (int kk = kk0; kk < kk0 + 4; ++kk) {
            int c0 = kk * 16 + 2 * t;
            int c2 = c0 + 8;
            float2 z = make_float2(0.f, 0.f);
            float2 p00 = v0 ? *(const float2*)(xr0 + c0) : z;
            float2 p10 = v1 ? *(const float2*)(xr1 + c0) : z;
            float2 p01 = v0 ? *(const float2*)(xr0 + c2) : z;
            float2 p11 = v1 ? *(const float2*)(xr1 + c2) : z;
            uint32_t h0, l0, h1, l1, h2, l2, h3, l3;
            split2(p00, h0, l0);
            split2(p10, h1, l1);
            split2(p01, h2, l2);
            split2(p11, h3, l3);
            *(uint4*)&sA[0][mf][kk][lane][0] = make_uint4(h0, h1, h2, h3);
            *(uint4*)&sA[1][mf][kk][lane][0] = make_uint4(l0, l1, l2, l3);
        }
    }
    __syncthreads();

    float acc[32];
    #pragma unroll
    for (int i = 0; i < 32; ++i) acc[i] = 0.f;

    const int row0 = m0 + wm * 16 + g;
    const int row1 = row0 + 8;

    #pragma unroll 1
    for (int cg = 0; cg < NMAT * 8; ++cg) {
        cp_wait<0>();
        __syncthreads();   // chunk cg ready; all warps done with chunk cg-1

        // prefetch next chunk into other buffer (overlaps with mma below)
        if (cg + 1 < NMAT * 8) {
            uint32_t sb = smem_u32(&sB[(cg + 1) & 1][0][0][0][0]);
            const char* src = (const char*)(g_wB + (size_t)(cg + 1) * 2048);
            cp16(sb + tid * 16, src + tid * 16);
            cp16(sb + 4096 + tid * 16, src + 4096 + tid * 16);
            cp_commit();
        }

        const int buf = cg & 1;
        const int kk  = cg & 7;
        uint4 ah = *(const uint4*)&sA[0][wm][kk][lane][0];
        uint4 al = *(const uint4*)&sA[1][wm][kk][lane][0];

        #pragma unroll
        for (int nf = 0; nf < 8; ++nf) {
            const int gnf = wn * 8 + nf;
            uint2 bh = *(const uint2*)&sB[buf][0][gnf][lane][0];
            uint2 bl = *(const uint2*)&sB[buf][1][gnf][lane][0];
            float* c = &acc[nf * 4];
            mma_bf16(c, ah.x, ah.y, ah.z, ah.w, bh.x, bh.y);
            mma_bf16(c, al.x, al.y, al.z, al.w, bh.x, bh.y);
            mma_bf16(c, ah.x, ah.y, ah.z, ah.w, bl.x, bl.y);
        }

        // ---- epilogue at end of each relation
        if (kk == 7) {
            const int r = cg >> 3;
            if (r < 8) {
                if (row0 < N_NODES) {
                    float* y0 = g_y + ((size_t)r * N_NODES + row0) * DIM + wn * 64;
                    #pragma unroll
                    for (int nf = 0; nf < 8; ++nf)
                        *(float2*)(y0 + nf * 8 + 2 * t) =
                            make_float2(acc[nf * 4 + 0], acc[nf * 4 + 1]);
                }
                if (row1 < N_NODES) {
                    float* y1 = g_y + ((size_t)r * N_NODES + row1) * DIM + wn * 64;
                    #pragma unroll
                    for (int nf = 0; nf < 8; ++nf)
                        *(float2*)(y1 + nf * 8 + 2 * t) =
                            make_float2(acc[nf * 4 + 2], acc[nf * 4 + 3]);
                }
            } else {
                #pragma unroll
                for (int nf = 0; nf < 8; ++nf) {
                    float2 bv = *(const float2*)(bias + wn * 64 + nf * 8 + 2 * t);
                    if (row0 < N_NODES)
                        *(float2*)(out + (size_t)row0 * DIM + wn * 64 + nf * 8 + 2 * t) =
                            make_float2(acc[nf * 4 + 0] + bv.x, acc[nf * 4 + 1] + bv.y);
                    if (row1 < N_NODES)
                        *(float2*)(out + (size_t)row1 * DIM + wn * 64 + nf * 8 + 2 * t) =
                            make_float2(acc[nf * 4 + 2] + bv.x, acc[nf * 4 + 3] + bv.y);
                }
            }
            #pragma unroll
            for (int i = 0; i < 32; ++i) acc[i] = 0.f;
        }
    }
}

// ---------------------------------------------------------------------------
// 4) scatter: one warp per edge: out[dst] += y[rel][src] * inv_deg[dst,rel]
//    vectorized red.global.add.v4.f32
// ---------------------------------------------------------------------------
__global__ void scatter_kernel(const void* __restrict__ ei,
                               const void* __restrict__ et,
                               float* __restrict__ out) {
    int gtid = blockIdx.x * blockDim.x + threadIdx.x;
    int e    = gtid >> 5;
    int lane = gtid & 31;
    if (e >= NEDGES) return;

    int is32 = g_is32;
    int src = load_idx(ei, e, is32);
    int dst = load_idx(ei, (long long)NEDGES + e, is32);
    int r   = load_idx(et, e, is32);
    float s = g_inv[dst * NREL + r];

    const float4 v = ((const float4*)(g_y + ((size_t)r * N_NODES + src) * DIM))[lane];
    float* o = out + (size_t)dst * DIM + lane * 4;
    asm volatile("red.global.add.v4.f32 [%0], {%1,%2,%3,%4};"
                 :: "l"(o), "f"(v.x * s), "f"(v.y * s), "f"(v.z * s), "f"(v.w * s)
                 : "memory");
}

// ---------------------------------------------------------------------------
// launch
// inputs: 0:x(f32), 1:edge_index, 2:edge_type, 3:rel_weight, 4:self_loop_weight,
//         5:bias
// ---------------------------------------------------------------------------
extern "C" void kernel_launch(void* const* d_in, const int* in_sizes, int n_in,
                              void* d_out, int out_size) {
    const float* x     = (const float*)d_in[0];
    const void*  ei    = d_in[1];
    const void*  et    = d_in[2];
    const float* wrel  = (const float*)d_in[3];
    const float* wself = (const float*)d_in[4];
    const float* bias  = (const float*)d_in[5];
    float*       out   = (float*)d_out;

    detect_kernel<<<1, 32>>>(ei);
    wprep_kernel<<<(NMAT * 8 * 2048 + 255) / 256, 256>>>(wrel, wself);
    zero_deg_kernel<<<(N_NODES * NREL + 255) / 256, 256>>>();
    deg_kernel<<<(NEDGES + 255) / 256, 256>>>(ei, et);
    inv_kernel<<<(N_NODES * NREL + 255) / 256, 256>>>();
    xw_kernel<<<(N_NODES + MTILE - 1) / MTILE, 256>>>(x, bias, out);
    scatter_kernel<<<((size_t)NEDGES * 32 + 255) / 256, 256>>>(ei, et, out);
}